// round 6
// baseline (speedup 1.0000x reference)
#include <cuda_runtime.h>
#include <mma.h>
#include <math.h>
#include <stdint.h>

using namespace nvcuda;

// Problem constants
#define B_    8
#define T_    2048
#define R_    (B_*T_)     // 16384 rows
#define VDIM_ 1024
#define ADIM_ 768
#define DM_   256
#define HID_  1024
#define XDIM_ 768         // 3*DM
#define NBLK_ 4           // HID / 256 column blocks for gate GEMM

// Scratch (__device__ globals; allocation-free rule)
__device__ __align__(16) float g_v[R_*DM_];      // raw video proj -> LN'd in place
__device__ float g_rv[R_];                       // 1/max(||v_row||,eps)
__device__ __align__(16) float g_a[R_*DM_];      // raw audio proj -> LN'd in place
__device__ __align__(16) float g_actx[R_*DM_];   // audio context (full precision)
__device__ __align__(16) float g_X[R_*XDIM_];    // [an, vn, an*vn], tf32-rounded
__device__ float g_plog[R_*NBLK_];               // partial logits
// tf32-rounded weights (stored as fp32)
__device__ __align__(16) float g_wv[VDIM_*DM_];
__device__ __align__(16) float g_wa[ADIM_*DM_];
__device__ __align__(16) float g_w1[XDIM_*HID_];

__device__ __forceinline__ float to_tf32(float x) {
    float r;
    asm("cvt.rna.tf32.f32 %0, %1;" : "=f"(r) : "f"(x));
    return r;
}
__device__ __forceinline__ uint32_t smem_u32(const void* p) {
    uint32_t a;
    asm("{ .reg .u64 t; cvta.to.shared.u64 t, %1; cvt.u32.u64 %0, t; }"
        : "=r"(a) : "l"(p));
    return a;
}
#define CP16(dst_u32, src_ptr) \
    asm volatile("cp.async.cg.shared.global [%0], [%1], 16;" \
                 :: "r"(dst_u32), "l"(src_ptr) : "memory")
#define CP_COMMIT() asm volatile("cp.async.commit_group;" ::: "memory")
#define CP_WAIT(n)  asm volatile("cp.async.wait_group %0;" :: "n"(n) : "memory")

// ---------------------------------------------------------------------------
// prep: rna-round weights to tf32, store as fp32 (so GEMM can cp.async raw).
// ---------------------------------------------------------------------------
__global__ __launch_bounds__(256) void prep_w(
    const float* __restrict__ W, float* __restrict__ Wo, int n4)
{
    int i = blockIdx.x * 256 + threadIdx.x;
    if (i < n4) {
        float4 v = ((const float4*)W)[i];
        v.x = to_tf32(v.x); v.y = to_tf32(v.y);
        v.z = to_tf32(v.z); v.w = to_tf32(v.w);
        ((float4*)Wo)[i] = v;
    }
}

// ---------------------------------------------------------------------------
// TF32 wmma GEMM, CTA tile 128x256, BK=32, 8 warps (2x4), warp tile 64x64.
// Double-buffered smem, compile-time chunk count NCH.
// Bt pre-rounded -> cp.async. A: AASYNC ? cp.async : reg-pipelined LDG/cvt/STS.
// EPI=0: raw C to Cout. EPI=1: mlp epilogue (bias + exact gelu . W2 reduce).
// ---------------------------------------------------------------------------
#define ALD 36                      // A smem ld (128 x 36)
#define BLD 260                     // B smem ld (32 x 260)
#define STGF (128*ALD + 32*BLD)     // 12928 floats per stage
#define CLD 260                     // epilogue C smem ld

template<int NCH, int NOUT, bool AASYNC, bool EPI>
__global__ __launch_bounds__(256) void gemm_big(
    const float* __restrict__ A, const float* __restrict__ Bt,
    const float* __restrict__ b1v, const float* __restrict__ W2v,
    float* __restrict__ Cout)
{
    extern __shared__ float sh[];
    const int tid  = threadIdx.x;
    const int lane = tid & 31;
    const int warp = tid >> 5;
    const int wr   = warp >> 2;         // 0..1 (64-row block)
    const int wc   = warp & 3;          // 0..3 (64-col block)
    const int row0 = blockIdx.x * 128;
    const int n0   = blockIdx.y * 256;
    const int KD   = NCH * 32;

    wmma::fragment<wmma::accumulator, 16, 16, 8, float> acc[4][4];
#pragma unroll
    for (int i = 0; i < 4; i++)
#pragma unroll
        for (int j = 0; j < 4; j++) wmma::fill_fragment(acc[i][j], 0.f);

    const int ar = tid >> 3;            // A copy: row 0..31 (+32*j)
    const int ac = (tid & 7) << 2;      // A copy: col 0,4,..,28
    const int br = tid >> 6;            // B copy: row 0..3 (+4*j)
    const int bc = (tid & 63) << 2;     // B copy: col 0..252

    float4 areg[4];

    auto ldgA = [&](int i) {
        const float* Ab = A + (size_t)row0 * KD + i * 32;
#pragma unroll
        for (int j = 0; j < 4; j++)
            areg[j] = *(const float4*)(Ab + (size_t)(ar + 32 * j) * KD + ac);
    };
    auto stsA = [&](float* As) {
#pragma unroll
        for (int j = 0; j < 4; j++) {
            float* d = As + (ar + 32 * j) * ALD + ac;
            d[0] = to_tf32(areg[j].x); d[1] = to_tf32(areg[j].y);
            d[2] = to_tf32(areg[j].z); d[3] = to_tf32(areg[j].w);
        }
    };
    auto cpA = [&](int i, float* As) {
        const float* Ab = A + (size_t)row0 * KD + i * 32;
#pragma unroll
        for (int j = 0; j < 4; j++)
            CP16(smem_u32(As + (ar + 32 * j) * ALD + ac),
                 Ab + (size_t)(ar + 32 * j) * KD + ac);
    };
    auto cpB = [&](int i, float* Bs) {
        const float* Wb = Bt + (size_t)(i * 32) * NOUT + n0;
#pragma unroll
        for (int j = 0; j < 8; j++)
            CP16(smem_u32(Bs + (br + 4 * j) * BLD + bc),
                 Wb + (size_t)(br + 4 * j) * NOUT + bc);
    };

    // Prologue: chunk 0 into stage 0
    {
        float* As0 = sh;
        float* Bs0 = sh + 128 * ALD;
        if (AASYNC) cpA(0, As0); else ldgA(0);
        cpB(0, Bs0);
        CP_COMMIT();
    }

#pragma unroll
    for (int i = 0; i < NCH; i++) {
        float* As = sh + (i & 1) * STGF;
        float* Bs = As + 128 * ALD;
        if (!AASYNC) stsA(As);                 // chunk i A into its stage
        if (i + 1 < NCH) {
            float* Asn = sh + ((i + 1) & 1) * STGF;
            if (AASYNC) cpA(i + 1, Asn);
            cpB(i + 1, Asn + 128 * ALD);
            CP_COMMIT();
            if (!AASYNC) ldgA(i + 1);          // hide LDG under chunk i compute
            CP_WAIT(1);
        } else {
            CP_WAIT(0);
        }
        __syncthreads();

#pragma unroll
        for (int kk = 0; kk < 32; kk += 8) {
            wmma::fragment<wmma::matrix_a, 16, 16, 8, wmma::precision::tf32,
                           wmma::row_major> af[4];
            wmma::fragment<wmma::matrix_b, 16, 16, 8, wmma::precision::tf32,
                           wmma::row_major> bf[4];
#pragma unroll
            for (int u = 0; u < 4; u++)
                wmma::load_matrix_sync(af[u],
                    As + (wr * 64 + u * 16) * ALD + kk, ALD);
#pragma unroll
            for (int v = 0; v < 4; v++)
                wmma::load_matrix_sync(bf[v],
                    Bs + kk * BLD + wc * 64 + v * 16, BLD);
#pragma unroll
            for (int u = 0; u < 4; u++)
#pragma unroll
                for (int v = 0; v < 4; v++)
                    wmma::mma_sync(acc[u][v], af[u], bf[v], acc[u][v]);
        }
        __syncthreads();
    }

    if (!EPI) {
#pragma unroll
        for (int u = 0; u < 4; u++)
#pragma unroll
            for (int v = 0; v < 4; v++)
                wmma::store_matrix_sync(
                    Cout + (size_t)(row0 + wr * 64 + u * 16) * NOUT
                         + n0 + wc * 64 + v * 16,
                    acc[u][v], NOUT, wmma::mem_row_major);
    } else {
        // stage C (128 x 256, ld 260) in smem, then bias+gelu.W2 row reduce
        float* Cs = sh;
#pragma unroll
        for (int u = 0; u < 4; u++)
#pragma unroll
            for (int v = 0; v < 4; v++)
                wmma::store_matrix_sync(
                    Cs + (wr * 64 + u * 16) * CLD + wc * 64 + v * 16,
                    acc[u][v], CLD, wmma::mem_row_major);
        __syncthreads();

        float b1f[8], w2f[8];
#pragma unroll
        for (int q = 0; q < 8; q++) {
            int gcol = n0 + lane + q * 32;
            b1f[q] = b1v[gcol];
            w2f[q] = W2v[gcol];
        }
#pragma unroll
        for (int rr = 0; rr < 16; rr++) {
            int r = warp * 16 + rr;
            float p = 0.f;
#pragma unroll
            for (int q = 0; q < 8; q++) {
                float x = Cs[r * CLD + lane + q * 32] + b1f[q];
                float h = 0.5f * x * (1.f + erff(x * 0.7071067811865476f));
                p = fmaf(h, w2f[q], p);
            }
#pragma unroll
            for (int off = 16; off > 0; off >>= 1)
                p += __shfl_xor_sync(0xffffffffu, p, off);
            if (lane == 0)
                g_plog[(size_t)(row0 + r) * NBLK_ + blockIdx.y] = p;
        }
    }
}

// ---------------------------------------------------------------------------
// LN pass: adds bias, LayerNorms in place. y=0 -> g_v (+g_rv), y=1 -> g_a.
// ---------------------------------------------------------------------------
__global__ __launch_bounds__(256) void ln_kernel(
    const float* __restrict__ bv, const float* __restrict__ ba)
{
    __shared__ float redS[8], redQ[8], bc2[2];
    const int row = blockIdx.x;
    const int d   = threadIdx.x;
    float* buf = blockIdx.y ? g_a : g_v;
    const float* bias = blockIdx.y ? ba : bv;

    float x = buf[(size_t)row * DM_ + d] + bias[d];
    float s = x, q = x * x;
#pragma unroll
    for (int off = 16; off > 0; off >>= 1) {
        s += __shfl_xor_sync(0xffffffffu, s, off);
        q += __shfl_xor_sync(0xffffffffu, q, off);
    }
    int lane = d & 31, warp = d >> 5;
    if (lane == 0) { redS[warp] = s; redQ[warp] = q; }
    __syncthreads();
    if (d == 0) {
        float ts = 0.f, tq = 0.f;
#pragma unroll
        for (int k = 0; k < 8; k++) { ts += redS[k]; tq += redQ[k]; }
        float mu  = ts * (1.f / 256.f);
        float var = fmaxf(tq * (1.f / 256.f) - mu * mu, 0.f);
        bc2[0] = mu;
        bc2[1] = rsqrtf(var + 1e-5f);
        if (blockIdx.y == 0) {
            float l2 = sqrtf(256.f * var) * bc2[1];
            g_rv[row] = 1.f / fmaxf(l2, 1e-8f);
        }
    }
    __syncthreads();
    buf[(size_t)row * DM_ + d] = (x - bc2[0]) * bc2[1];
}

// ---------------------------------------------------------------------------
// ctx: temporal shift + causal 6-tap window avg + l2 norms + build X
// (X stored tf32-rounded so mlp GEMM can cp.async it raw).
// 4 rows/block, 64 threads/row, float4 per thread. center==t (delta in (2,6)).
// ---------------------------------------------------------------------------
__global__ __launch_bounds__(256) void ctx_kernel(const float* __restrict__ theta)
{
    __shared__ float red2[4][2];
    const int tid = threadIdx.x;
    const int rl  = tid >> 6;
    const int q   = tid & 63;
    const int row = blockIdx.x * 4 + rl;
    const int b   = row >> 11;
    const int t   = row & 2047;

    float th    = fminf(fmaxf(theta[0], -12.f), 12.f);
    float delta = 2.f + 4.f / (1.f + expf(-th));
    float nf    = floorf(delta);
    float alpha = delta - nf;
    int   ni    = (int)nf;

    const int lo = max(0, t - 5);
    const float inv_cnt = 1.f / (float)(t - lo + 1);

    const float* ab = g_a + (size_t)b * T_ * DM_;
    float4 acc = {0.f, 0.f, 0.f, 0.f};
    for (int tau = lo; tau <= t; tau++) {
        int i0 = min(max(tau - ni, 0), T_ - 1);
        int i1 = min(i0 + 1, T_ - 1);
        float4 x0 = *(const float4*)(ab + (size_t)i0 * DM_ + q * 4);
        float4 x1 = *(const float4*)(ab + (size_t)i1 * DM_ + q * 4);
        acc.x += (1.f - alpha) * x0.x + alpha * x1.x;
        acc.y += (1.f - alpha) * x0.y + alpha * x1.y;
        acc.z += (1.f - alpha) * x0.z + alpha * x1.z;
        acc.w += (1.f - alpha) * x0.w + alpha * x1.w;
    }
    float4 ac = {acc.x * inv_cnt, acc.y * inv_cnt, acc.z * inv_cnt, acc.w * inv_cnt};

    float ss = ac.x * ac.x + ac.y * ac.y + ac.z * ac.z + ac.w * ac.w;
#pragma unroll
    for (int off = 16; off > 0; off >>= 1)
        ss += __shfl_xor_sync(0xffffffffu, ss, off);
    const int wp = tid >> 5;
    if ((tid & 31) == 0) red2[wp >> 1][wp & 1] = ss;
    __syncthreads();
    float tot = red2[rl][0] + red2[rl][1];
    float ra  = 1.f / fmaxf(sqrtf(tot), 1e-8f);

    float4 vv = *(const float4*)(g_v + (size_t)row * DM_ + q * 4);
    float rv  = g_rv[row];

    *(float4*)(g_actx + (size_t)row * DM_ + q * 4) = ac;

    float4 vn = {to_tf32(vv.x * rv), to_tf32(vv.y * rv),
                 to_tf32(vv.z * rv), to_tf32(vv.w * rv)};
    float4 an = {to_tf32(ac.x * ra), to_tf32(ac.y * ra),
                 to_tf32(ac.z * ra), to_tf32(ac.w * ra)};
    float4 pr = {to_tf32(an.x * vn.x), to_tf32(an.y * vn.y),
                 to_tf32(an.z * vn.z), to_tf32(an.w * vn.w)};

    float* xr = g_X + (size_t)row * XDIM_;
    *(float4*)(xr + q * 4)           = an;
    *(float4*)(xr + DM_ + q * 4)     = vn;
    *(float4*)(xr + 2 * DM_ + q * 4) = pr;
}

// ---------------------------------------------------------------------------
// out: finish logit, gate, mix. float4 per thread.
// ---------------------------------------------------------------------------
__global__ __launch_bounds__(256) void out_kernel(
    const float* __restrict__ b2, float* __restrict__ out)
{
    const int idx = blockIdx.x * 256 + threadIdx.x;   // over R_*64 float4s
    const int row = idx >> 6;
    const int c4  = (idx & 63) << 2;
    float s = b2[0];
#pragma unroll
    for (int k = 0; k < NBLK_; k++) s += g_plog[(size_t)row * NBLK_ + k];
    s = fminf(fmaxf(s, -12.f), 12.f);
    float g = 1.f / (1.f + expf(-s));
    g = fminf(fmaxf(g, 0.05f), 0.95f);
    float4 ac = *(const float4*)(g_actx + (size_t)row * DM_ + c4);
    float4 vv = *(const float4*)(g_v + (size_t)row * DM_ + c4);
    float4 o  = {g * ac.x + (1.f - g) * vv.x, g * ac.y + (1.f - g) * vv.y,
                 g * ac.z + (1.f - g) * vv.z, g * ac.w + (1.f - g) * vv.w};
    *(float4*)(out + (size_t)row * DM_ + c4) = o;
}

// ---------------------------------------------------------------------------
extern "C" void kernel_launch(void* const* d_in, const int* in_sizes, int n_in,
                              void* d_out, int out_size)
{
    const float* video = (const float*)d_in[0];
    const float* audio = (const float*)d_in[1];
    const float* Wv    = (const float*)d_in[2];
    const float* bv    = (const float*)d_in[3];
    const float* Wa    = (const float*)d_in[4];
    const float* ba    = (const float*)d_in[5];
    const float* theta = (const float*)d_in[6];
    const float* W1    = (const float*)d_in[7];
    const float* b1    = (const float*)d_in[8];
    const float* W2    = (const float*)d_in[9];
    const float* b2    = (const float*)d_in[10];
    float* out = (float*)d_out;

    float *gv, *ga, *gx, *wv, *wa, *w1;
    cudaGetSymbolAddress((void**)&gv, g_v);
    cudaGetSymbolAddress((void**)&ga, g_a);
    cudaGetSymbolAddress((void**)&gx, g_X);
    cudaGetSymbolAddress((void**)&wv, g_wv);
    cudaGetSymbolAddress((void**)&wa, g_wa);
    cudaGetSymbolAddress((void**)&w1, g_w1);

    const int gsm  = 2 * STGF * sizeof(float);        // 103424 B
    const int msm  = 128 * CLD * sizeof(float);       // 133120 B (epilogue C)
    cudaFuncSetAttribute(gemm_big<VDIM_/32, DM_, false, false>,
        cudaFuncAttributeMaxDynamicSharedMemorySize, gsm);
    cudaFuncSetAttribute(gemm_big<ADIM_/32, DM_, false, false>,
        cudaFuncAttributeMaxDynamicSharedMemorySize, gsm);
    cudaFuncSetAttribute(gemm_big<XDIM_/32, HID_, true, true>,
        cudaFuncAttributeMaxDynamicSharedMemorySize, msm);

    // weight prep (rna tf32 rounding, stored as fp32)
    prep_w<<<(VDIM_*DM_/4 + 255)/256, 256>>>(Wv, wv, VDIM_*DM_/4);
    prep_w<<<(ADIM_*DM_/4 + 255)/256, 256>>>(Wa, wa, ADIM_*DM_/4);
    prep_w<<<(XDIM_*HID_/4 + 255)/256, 256>>>(W1, w1, XDIM_*HID_/4);

    gemm_big<VDIM_/32, DM_, false, false><<<dim3(R_/128, 1), 256, gsm>>>(
        video, wv, nullptr, nullptr, gv);
    gemm_big<ADIM_/32, DM_, false, false><<<dim3(R_/128, 1), 256, gsm>>>(
        audio, wa, nullptr, nullptr, ga);
    ln_kernel<<<dim3(R_, 2), 256>>>(bv, ba);
    ctx_kernel<<<R_/4, 256>>>(theta);
    gemm_big<XDIM_/32, HID_, true, true><<<dim3(R_/128, HID_/256), 256, msm>>>(
        gx, w1, b1, W2, nullptr);
    out_kernel<<<(R_*64)/256, 256>>>(b2, out);
}

// round 7
// speedup vs baseline: 4.2556x; 4.2556x over previous
#include <cuda_runtime.h>
#include <cuda_fp16.h>
#include <mma.h>
#include <math.h>
#include <stdint.h>

using namespace nvcuda;

// Problem constants
#define B_    8
#define T_    2048
#define R_    (B_*T_)     // 16384 rows
#define VDIM_ 1024
#define ADIM_ 768
#define DM_   256
#define HID_  1024
#define XDIM_ 768         // 3*DM
#define NBLK_ 8           // HID / 128 column blocks for gate GEMM

// Scratch (__device__ globals; allocation-free rule)
__device__ __align__(16) float g_v[R_*DM_];      // raw video proj -> LN'd in place
__device__ float g_rv[R_];                       // 1/max(||v_row||,eps)
__device__ __align__(16) float g_a[R_*DM_];      // raw audio proj -> LN'd in place
__device__ __align__(16) float g_actx[R_*DM_];   // audio context (full precision)
__device__ __align__(16) __half g_Xh[R_*XDIM_];  // [an, vn, an*vn] in fp16
__device__ float g_plog[R_*NBLK_];               // partial logits
// fp16 weights
__device__ __align__(16) __half g_wv[VDIM_*DM_];
__device__ __align__(16) __half g_wa[ADIM_*DM_];
__device__ __align__(16) __half g_w1[XDIM_*HID_];

__device__ __forceinline__ uint32_t smem_u32(const void* p) {
    uint32_t a;
    asm("{ .reg .u64 t; cvta.to.shared.u64 t, %1; cvt.u32.u64 %0, t; }"
        : "=r"(a) : "l"(p));
    return a;
}
#define CP16(dst_u32, src_ptr) \
    asm volatile("cp.async.cg.shared.global [%0], [%1], 16;" \
                 :: "r"(dst_u32), "l"(src_ptr) : "memory")
#define CP_COMMIT() asm volatile("cp.async.commit_group;" ::: "memory")
#define CP_WAIT(n)  asm volatile("cp.async.wait_group %0;" :: "n"(n) : "memory")

__device__ __forceinline__ uint32_t pkh2(float a, float b) {
    __half2 h = __floats2half2_rn(a, b);
    return *reinterpret_cast<uint32_t*>(&h);
}

// ---------------------------------------------------------------------------
// prep: convert weights fp32 -> fp16.
// ---------------------------------------------------------------------------
__global__ __launch_bounds__(256) void prep_wh(
    const float* __restrict__ W, __half* __restrict__ Wo, int n4)
{
    int i = blockIdx.x * 256 + threadIdx.x;
    if (i < n4) {
        float4 v = ((const float4*)W)[i];
        uint2 o = make_uint2(pkh2(v.x, v.y), pkh2(v.z, v.w));
        *(uint2*)(Wo + (size_t)i * 4) = o;
    }
}

// ---------------------------------------------------------------------------
// FP16 wmma GEMM (fp32 accum): C[R x NOUT] = A[R x KD] @ Bt[KD x NOUT].
// CTA tile 128x128, BK=32 (2 kk-steps of k16), 256 thr, 8 warps (4x2),
// warp tile 32x64, double-buffered smem, compile-time NCH.
// Bt fp16 -> cp.async. A: AASYNC ? cp.async (fp16 src) : LDG fp32 -> cvt -> STS.
// EPI=0: raw fp32 C to Cout. EPI=1: mlp epilogue (bias + exact gelu . W2).
// Smem halves layout per stage: A 128x40, B 32x136 (LDSM-conflict-free pads).
// ---------------------------------------------------------------------------
#define ALDH 40                      // A smem leading dim (halves)
#define BLDH 136                     // B smem leading dim (halves)
#define AHALF (128*ALDH)             // 5120 halves
#define STGH (AHALF + 32*BLDH)       // 9472 halves = 18944 B per stage

template<int NCH, int NOUT, bool AASYNC, bool EPI>
__global__ __launch_bounds__(256) void gemm_h(
    const void* __restrict__ Ap, const __half* __restrict__ Bt,
    const float* __restrict__ b1v, const float* __restrict__ W2v,
    float* __restrict__ Cout)
{
    extern __shared__ __align__(16) char smraw[];
    __half* sh = (__half*)smraw;
    const int tid  = threadIdx.x;
    const int lane = tid & 31;
    const int warp = tid >> 5;
    const int wr   = warp >> 1;         // 0..3 (32-row block)
    const int wc   = warp & 1;          // 0..1 (64-col block)
    const int row0 = blockIdx.x * 128;
    const int n0   = blockIdx.y * 128;
    const int KD   = NCH * 32;

    wmma::fragment<wmma::accumulator, 16, 16, 16, float> acc[2][4];
#pragma unroll
    for (int i = 0; i < 2; i++)
#pragma unroll
        for (int j = 0; j < 4; j++) wmma::fill_fragment(acc[i][j], 0.f);

    // sync-A path mapping (proj): 16 floats/thread
    const int ar = tid >> 3;            // rows 0..31 (+32*j)
    const int ac = (tid & 7) << 2;      // cols 0,4,..,28

    float4 areg[4];

    auto ldgA = [&](int i) {
        const float* Af = (const float*)Ap;
        const float* Ab = Af + (size_t)row0 * KD + i * 32;
#pragma unroll
        for (int j = 0; j < 4; j++)
            areg[j] = *(const float4*)(Ab + (size_t)(ar + 32 * j) * KD + ac);
    };
    auto stsA = [&](__half* As) {
#pragma unroll
        for (int j = 0; j < 4; j++) {
            uint2 o = make_uint2(pkh2(areg[j].x, areg[j].y),
                                 pkh2(areg[j].z, areg[j].w));
            *(uint2*)(As + (ar + 32 * j) * ALDH + ac) = o;
        }
    };
    auto cpA = [&](int i, __half* As) {
        const __half* Ah = (const __half*)Ap;
        // 128 rows x 4 segs of 8 halves = 512 CP16s
#pragma unroll
        for (int j = 0; j < 2; j++) {
            int idx = tid + j * 256;
            int r   = idx >> 2;
            int sg  = (idx & 3) << 3;
            CP16(smem_u32(As + r * ALDH + sg),
                 Ah + (size_t)(row0 + r) * KD + i * 32 + sg);
        }
    };
    auto cpB = [&](int i, __half* Bs) {
        // 32 rows x 16 segs of 8 halves = 512 CP16s
#pragma unroll
        for (int j = 0; j < 2; j++) {
            int idx = tid + j * 256;
            int r   = idx >> 4;
            int sg  = (idx & 15) << 3;
            CP16(smem_u32(Bs + r * BLDH + sg),
                 Bt + (size_t)(i * 32 + r) * NOUT + n0 + sg);
        }
    };

    // Prologue: chunk 0 into stage 0
    {
        __half* As0 = sh;
        __half* Bs0 = sh + AHALF;
        if (AASYNC) cpA(0, As0); else ldgA(0);
        cpB(0, Bs0);
        CP_COMMIT();
    }

#pragma unroll
    for (int i = 0; i < NCH; i++) {
        __half* As = sh + (i & 1) * STGH;
        __half* Bs = As + AHALF;
        if (!AASYNC) stsA(As);                 // chunk i A into its stage
        if (i + 1 < NCH) {
            __half* Asn = sh + ((i + 1) & 1) * STGH;
            if (AASYNC) cpA(i + 1, Asn);
            cpB(i + 1, Asn + AHALF);
            CP_COMMIT();
            if (!AASYNC) ldgA(i + 1);          // hide LDG under chunk i compute
            CP_WAIT(1);
        } else {
            CP_WAIT(0);
        }
        __syncthreads();

#pragma unroll
        for (int kk = 0; kk < 32; kk += 16) {
            wmma::fragment<wmma::matrix_a, 16, 16, 16, __half,
                           wmma::row_major> af[2];
            wmma::fragment<wmma::matrix_b, 16, 16, 16, __half,
                           wmma::row_major> bf[4];
#pragma unroll
            for (int u = 0; u < 2; u++)
                wmma::load_matrix_sync(af[u],
                    As + (wr * 32 + u * 16) * ALDH + kk, ALDH);
#pragma unroll
            for (int v = 0; v < 4; v++)
                wmma::load_matrix_sync(bf[v],
                    Bs + kk * BLDH + wc * 64 + v * 16, BLDH);
#pragma unroll
            for (int u = 0; u < 2; u++)
#pragma unroll
                for (int v = 0; v < 4; v++)
                    wmma::mma_sync(acc[u][v], af[u], bf[v], acc[u][v]);
        }
        __syncthreads();
    }

    if (!EPI) {
#pragma unroll
        for (int u = 0; u < 2; u++)
#pragma unroll
            for (int v = 0; v < 4; v++)
                wmma::store_matrix_sync(
                    Cout + (size_t)(row0 + wr * 32 + u * 16) * NOUT
                         + n0 + wc * 64 + v * 16,
                    acc[u][v], NOUT, wmma::mem_row_major);
    } else {
        // stage C (128 x 132 fp32) in smem, then bias + gelu . W2 row reduce
        float* Cs = (float*)smraw;
#pragma unroll
        for (int u = 0; u < 2; u++)
#pragma unroll
            for (int v = 0; v < 4; v++)
                wmma::store_matrix_sync(
                    Cs + (wr * 32 + u * 16) * 132 + wc * 64 + v * 16,
                    acc[u][v], 132, wmma::mem_row_major);
        __syncthreads();

        float b1f[4], w2f[4];
#pragma unroll
        for (int q = 0; q < 4; q++) {
            int gcol = n0 + lane + q * 32;
            b1f[q] = b1v[gcol];
            w2f[q] = W2v[gcol];
        }
#pragma unroll
        for (int rr = 0; rr < 16; rr++) {
            int r = warp * 16 + rr;
            float p = 0.f;
#pragma unroll
            for (int q = 0; q < 4; q++) {
                float x = Cs[r * 132 + lane + q * 32] + b1f[q];
                float h = 0.5f * x * (1.f + erff(x * 0.7071067811865476f));
                p = fmaf(h, w2f[q], p);
            }
#pragma unroll
            for (int off = 16; off > 0; off >>= 1)
                p += __shfl_xor_sync(0xffffffffu, p, off);
            if (lane == 0)
                g_plog[(size_t)(row0 + r) * NBLK_ + blockIdx.y] = p;
        }
    }
}

// ---------------------------------------------------------------------------
// LN pass: adds bias, LayerNorms in place. y=0 -> g_v (+g_rv), y=1 -> g_a.
// ---------------------------------------------------------------------------
__global__ __launch_bounds__(256) void ln_kernel(
    const float* __restrict__ bv, const float* __restrict__ ba)
{
    __shared__ float redS[8], redQ[8], bc2[2];
    const int row = blockIdx.x;
    const int d   = threadIdx.x;
    float* buf = blockIdx.y ? g_a : g_v;
    const float* bias = blockIdx.y ? ba : bv;

    float x = buf[(size_t)row * DM_ + d] + bias[d];
    float s = x, q = x * x;
#pragma unroll
    for (int off = 16; off > 0; off >>= 1) {
        s += __shfl_xor_sync(0xffffffffu, s, off);
        q += __shfl_xor_sync(0xffffffffu, q, off);
    }
    int lane = d & 31, warp = d >> 5;
    if (lane == 0) { redS[warp] = s; redQ[warp] = q; }
    __syncthreads();
    if (d == 0) {
        float ts = 0.f, tq = 0.f;
#pragma unroll
        for (int k = 0; k < 8; k++) { ts += redS[k]; tq += redQ[k]; }
        float mu  = ts * (1.f / 256.f);
        float var = fmaxf(tq * (1.f / 256.f) - mu * mu, 0.f);
        bc2[0] = mu;
        bc2[1] = rsqrtf(var + 1e-5f);
        if (blockIdx.y == 0) {
            float l2 = sqrtf(256.f * var) * bc2[1];
            g_rv[row] = 1.f / fmaxf(l2, 1e-8f);
        }
    }
    __syncthreads();
    buf[(size_t)row * DM_ + d] = (x - bc2[0]) * bc2[1];
}

// ---------------------------------------------------------------------------
// ctx: temporal shift + causal 6-tap window avg + l2 norms + build X (fp16).
// 4 rows/block, 64 threads/row, float4 per thread. center==t (delta in (2,6)).
// ---------------------------------------------------------------------------
__global__ __launch_bounds__(256) void ctx_kernel(const float* __restrict__ theta)
{
    __shared__ float red2[4][2];
    const int tid = threadIdx.x;
    const int rl  = tid >> 6;
    const int q   = tid & 63;
    const int row = blockIdx.x * 4 + rl;
    const int b   = row >> 11;
    const int t   = row & 2047;

    float th    = fminf(fmaxf(theta[0], -12.f), 12.f);
    float delta = 2.f + 4.f / (1.f + expf(-th));
    float nf    = floorf(delta);
    float alpha = delta - nf;
    int   ni    = (int)nf;

    const int lo = max(0, t - 5);
    const float inv_cnt = 1.f / (float)(t - lo + 1);

    const float* ab = g_a + (size_t)b * T_ * DM_;
    float4 acc = {0.f, 0.f, 0.f, 0.f};
    for (int tau = lo; tau <= t; tau++) {
        int i0 = min(max(tau - ni, 0), T_ - 1);
        int i1 = min(i0 + 1, T_ - 1);
        float4 x0 = *(const float4*)(ab + (size_t)i0 * DM_ + q * 4);
        float4 x1 = *(const float4*)(ab + (size_t)i1 * DM_ + q * 4);
        acc.x += (1.f - alpha) * x0.x + alpha * x1.x;
        acc.y += (1.f - alpha) * x0.y + alpha * x1.y;
        acc.z += (1.f - alpha) * x0.z + alpha * x1.z;
        acc.w += (1.f - alpha) * x0.w + alpha * x1.w;
    }
    float4 ac = {acc.x * inv_cnt, acc.y * inv_cnt, acc.z * inv_cnt, acc.w * inv_cnt};

    float ss = ac.x * ac.x + ac.y * ac.y + ac.z * ac.z + ac.w * ac.w;
#pragma unroll
    for (int off = 16; off > 0; off >>= 1)
        ss += __shfl_xor_sync(0xffffffffu, ss, off);
    const int wp = tid >> 5;
    if ((tid & 31) == 0) red2[wp >> 1][wp & 1] = ss;
    __syncthreads();
    float tot = red2[rl][0] + red2[rl][1];
    float ra  = 1.f / fmaxf(sqrtf(tot), 1e-8f);

    float4 vv = *(const float4*)(g_v + (size_t)row * DM_ + q * 4);
    float rv  = g_rv[row];

    *(float4*)(g_actx + (size_t)row * DM_ + q * 4) = ac;

    float vnx = vv.x * rv, vny = vv.y * rv, vnz = vv.z * rv, vnw = vv.w * rv;
    float anx = ac.x * ra, any_ = ac.y * ra, anz = ac.z * ra, anw = ac.w * ra;

    __half* xr = g_Xh + (size_t)row * XDIM_;
    *(uint2*)(xr + q * 4) =
        make_uint2(pkh2(anx, any_), pkh2(anz, anw));
    *(uint2*)(xr + DM_ + q * 4) =
        make_uint2(pkh2(vnx, vny), pkh2(vnz, vnw));
    *(uint2*)(xr + 2 * DM_ + q * 4) =
        make_uint2(pkh2(anx * vnx, any_ * vny), pkh2(anz * vnz, anw * vnw));
}

// ---------------------------------------------------------------------------
// out: finish logit, gate, mix. float4 per thread.
// ---------------------------------------------------------------------------
__global__ __launch_bounds__(256) void out_kernel(
    const float* __restrict__ b2, float* __restrict__ out)
{
    const int idx = blockIdx.x * 256 + threadIdx.x;   // over R_*64 float4s
    const int row = idx >> 6;
    const int c4  = (idx & 63) << 2;
    float s = b2[0];
#pragma unroll
    for (int k = 0; k < NBLK_; k++) s += g_plog[(size_t)row * NBLK_ + k];
    s = fminf(fmaxf(s, -12.f), 12.f);
    float g = 1.f / (1.f + expf(-s));
    g = fminf(fmaxf(g, 0.05f), 0.95f);
    float4 ac = *(const float4*)(g_actx + (size_t)row * DM_ + c4);
    float4 vv = *(const float4*)(g_v + (size_t)row * DM_ + c4);
    float4 o  = {g * ac.x + (1.f - g) * vv.x, g * ac.y + (1.f - g) * vv.y,
                 g * ac.z + (1.f - g) * vv.z, g * ac.w + (1.f - g) * vv.w};
    *(float4*)(out + (size_t)row * DM_ + c4) = o;
}

// ---------------------------------------------------------------------------
extern "C" void kernel_launch(void* const* d_in, const int* in_sizes, int n_in,
                              void* d_out, int out_size)
{
    const float* video = (const float*)d_in[0];
    const float* audio = (const float*)d_in[1];
    const float* Wv    = (const float*)d_in[2];
    const float* bv    = (const float*)d_in[3];
    const float* Wa    = (const float*)d_in[4];
    const float* ba    = (const float*)d_in[5];
    const float* theta = (const float*)d_in[6];
    const float* W1    = (const float*)d_in[7];
    const float* b1    = (const float*)d_in[8];
    const float* W2    = (const float*)d_in[9];
    const float* b2    = (const float*)d_in[10];
    float* out = (float*)d_out;

    float *gv, *ga;
    __half *gxh, *wv, *wa, *w1;
    cudaGetSymbolAddress((void**)&gv,  g_v);
    cudaGetSymbolAddress((void**)&ga,  g_a);
    cudaGetSymbolAddress((void**)&gxh, g_Xh);
    cudaGetSymbolAddress((void**)&wv,  g_wv);
    cudaGetSymbolAddress((void**)&wa,  g_wa);
    cudaGetSymbolAddress((void**)&w1,  g_w1);

    const int gsm = 2 * STGH * sizeof(__half);        // 37888 B
    const int msm = 128 * 132 * sizeof(float);        // 67584 B (epilogue C)
    cudaFuncSetAttribute(gemm_h<VDIM_/32, DM_, false, false>,
        cudaFuncAttributeMaxDynamicSharedMemorySize, gsm);
    cudaFuncSetAttribute(gemm_h<ADIM_/32, DM_, false, false>,
        cudaFuncAttributeMaxDynamicSharedMemorySize, gsm);
    cudaFuncSetAttribute(gemm_h<XDIM_/32, HID_, true, true>,
        cudaFuncAttributeMaxDynamicSharedMemorySize, msm);

    // weight prep (fp32 -> fp16)
    prep_wh<<<(VDIM_*DM_/4 + 255)/256, 256>>>(Wv, wv, VDIM_*DM_/4);
    prep_wh<<<(ADIM_*DM_/4 + 255)/256, 256>>>(Wa, wa, ADIM_*DM_/4);
    prep_wh<<<(XDIM_*HID_/4 + 255)/256, 256>>>(W1, w1, XDIM_*HID_/4);

    gemm_h<VDIM_/32, DM_, false, false><<<dim3(R_/128, 2), 256, gsm>>>(
        video, wv, nullptr, nullptr, gv);
    gemm_h<ADIM_/32, DM_, false, false><<<dim3(R_/128, 2), 256, gsm>>>(
        audio, wa, nullptr, nullptr, ga);
    ln_kernel<<<dim3(R_, 2), 256>>>(bv, ba);
    ctx_kernel<<<R_/4, 256>>>(theta);
    gemm_h<XDIM_/32, HID_, true, true><<<dim3(R_/128, NBLK_), 256, msm>>>(
        gxh, w1, b1, W2, nullptr);
    out_kernel<<<(R_*64)/256, 256>>>(b2, out);
}

// round 8
// speedup vs baseline: 4.8822x; 1.1472x over previous
#include <cuda_runtime.h>
#include <cuda_fp16.h>
#include <mma.h>
#include <math.h>
#include <stdint.h>

using namespace nvcuda;

// Problem constants
#define B_    8
#define T_    2048
#define R_    (B_*T_)     // 16384 rows
#define VDIM_ 1024
#define ADIM_ 768
#define DM_   256
#define HID_  1024
#define XDIM_ 768         // 3*DM
#define NBLK_ 8           // HID / 128 column blocks for gate GEMM

// Scratch (__device__ globals; allocation-free rule)
__device__ __align__(16) float g_v[R_*DM_];      // raw video proj -> LN'd in place
__device__ float g_rv[R_];                       // 1/max(||v_row||,eps)
__device__ __align__(16) float g_a[R_*DM_];      // raw audio proj -> LN'd in place
__device__ __align__(16) float g_actx[R_*DM_];   // audio context (full precision)
__device__ __align__(16) __half g_Xh[R_*XDIM_];  // [an, vn, an*vn] in fp16
__device__ float g_plog[R_*NBLK_];               // partial logits
// fp16 weights
__device__ __align__(16) __half g_wv[VDIM_*DM_];
__device__ __align__(16) __half g_wa[ADIM_*DM_];
__device__ __align__(16) __half g_w1[XDIM_*HID_];

__device__ __forceinline__ uint32_t smem_u32(const void* p) {
    uint32_t a;
    asm("{ .reg .u64 t; cvta.to.shared.u64 t, %1; cvt.u32.u64 %0, t; }"
        : "=r"(a) : "l"(p));
    return a;
}
#define CP16(dst_u32, src_ptr) \
    asm volatile("cp.async.cg.shared.global [%0], [%1], 16;" \
                 :: "r"(dst_u32), "l"(src_ptr) : "memory")
#define CP_COMMIT() asm volatile("cp.async.commit_group;" ::: "memory")
#define CP_WAIT(n)  asm volatile("cp.async.wait_group %0;" :: "n"(n) : "memory")

__device__ __forceinline__ uint32_t pkh2(float a, float b) {
    __half2 h = __floats2half2_rn(a, b);
    return *reinterpret_cast<uint32_t*>(&h);
}

// ---------------------------------------------------------------------------
// prep: convert weights fp32 -> fp16.
// ---------------------------------------------------------------------------
__global__ __launch_bounds__(256) void prep_wh(
    const float* __restrict__ W, __half* __restrict__ Wo, int n4)
{
    int i = blockIdx.x * 256 + threadIdx.x;
    if (i < n4) {
        float4 v = ((const float4*)W)[i];
        uint2 o = make_uint2(pkh2(v.x, v.y), pkh2(v.z, v.w));
        *(uint2*)(Wo + (size_t)i * 4) = o;
    }
}

// ---------------------------------------------------------------------------
// FP16 wmma GEMM (fp32 accum): C[R x NOUT] = A[R x KD] @ Bt[KD x NOUT].
// CTA tile 128x128, BK=32 (2 kk-steps of k16), 256 thr, 8 warps (4x2),
// warp tile 32x64, double-buffered smem, compile-time NCH.
// __launch_bounds__(256,2): cap regs at 128 so 2 CTAs co-reside per SM --
// their barrier/LDSM shadows interleave with each other's HMMA bursts.
// Bt fp16 -> cp.async. A: AASYNC ? cp.async (fp16 src) : LDG fp32 -> cvt -> STS.
// EPI=0: raw fp32 C to Cout. EPI=1: mlp epilogue (bias + exact gelu . W2).
// ---------------------------------------------------------------------------
#define ALDH 40                      // A smem leading dim (halves)
#define BLDH 136                     // B smem leading dim (halves)
#define AHALF (128*ALDH)             // 5120 halves
#define STGH (AHALF + 32*BLDH)       // 9472 halves = 18944 B per stage

template<int NCH, int NOUT, bool AASYNC, bool EPI>
__global__ __launch_bounds__(256, 2) void gemm_h(
    const void* __restrict__ Ap, const __half* __restrict__ Bt,
    const float* __restrict__ b1v, const float* __restrict__ W2v,
    float* __restrict__ Cout)
{
    extern __shared__ __align__(16) char smraw[];
    __half* sh = (__half*)smraw;
    const int tid  = threadIdx.x;
    const int lane = tid & 31;
    const int warp = tid >> 5;
    const int wr   = warp >> 1;         // 0..3 (32-row block)
    const int wc   = warp & 1;          // 0..1 (64-col block)
    const int row0 = blockIdx.x * 128;
    const int n0   = blockIdx.y * 128;
    const int KD   = NCH * 32;

    wmma::fragment<wmma::accumulator, 16, 16, 16, float> acc[2][4];
#pragma unroll
    for (int i = 0; i < 2; i++)
#pragma unroll
        for (int j = 0; j < 4; j++) wmma::fill_fragment(acc[i][j], 0.f);

    // sync-A path mapping (proj): 16 floats/thread
    const int ar = tid >> 3;            // rows 0..31 (+32*j)
    const int ac = (tid & 7) << 2;      // cols 0,4,..,28

    float4 areg[4];

    auto ldgA = [&](int i) {
        const float* Af = (const float*)Ap;
        const float* Ab = Af + (size_t)row0 * KD + i * 32;
#pragma unroll
        for (int j = 0; j < 4; j++)
            areg[j] = *(const float4*)(Ab + (size_t)(ar + 32 * j) * KD + ac);
    };
    auto stsA = [&](__half* As) {
#pragma unroll
        for (int j = 0; j < 4; j++) {
            uint2 o = make_uint2(pkh2(areg[j].x, areg[j].y),
                                 pkh2(areg[j].z, areg[j].w));
            *(uint2*)(As + (ar + 32 * j) * ALDH + ac) = o;
        }
    };
    auto cpA = [&](int i, __half* As) {
        const __half* Ah = (const __half*)Ap;
#pragma unroll
        for (int j = 0; j < 2; j++) {
            int idx = tid + j * 256;
            int r   = idx >> 2;
            int sg  = (idx & 3) << 3;
            CP16(smem_u32(As + r * ALDH + sg),
                 Ah + (size_t)(row0 + r) * KD + i * 32 + sg);
        }
    };
    auto cpB = [&](int i, __half* Bs) {
#pragma unroll
        for (int j = 0; j < 2; j++) {
            int idx = tid + j * 256;
            int r   = idx >> 4;
            int sg  = (idx & 15) << 3;
            CP16(smem_u32(Bs + r * BLDH + sg),
                 Bt + (size_t)(i * 32 + r) * NOUT + n0 + sg);
        }
    };

    // Prologue: chunk 0 into stage 0
    {
        __half* As0 = sh;
        __half* Bs0 = sh + AHALF;
        if (AASYNC) cpA(0, As0); else ldgA(0);
        cpB(0, Bs0);
        CP_COMMIT();
    }

#pragma unroll
    for (int i = 0; i < NCH; i++) {
        __half* As = sh + (i & 1) * STGH;
        __half* Bs = As + AHALF;
        if (!AASYNC) stsA(As);                 // chunk i A into its stage
        if (i + 1 < NCH) {
            __half* Asn = sh + ((i + 1) & 1) * STGH;
            if (AASYNC) cpA(i + 1, Asn);
            cpB(i + 1, Asn + AHALF);
            CP_COMMIT();
            if (!AASYNC) ldgA(i + 1);          // hide LDG under chunk i compute
            CP_WAIT(1);
        } else {
            CP_WAIT(0);
        }
        __syncthreads();

#pragma unroll
        for (int kk = 0; kk < 32; kk += 16) {
            wmma::fragment<wmma::matrix_a, 16, 16, 16, __half,
                           wmma::row_major> af[2];
            wmma::fragment<wmma::matrix_b, 16, 16, 16, __half,
                           wmma::row_major> bf[4];
#pragma unroll
            for (int u = 0; u < 2; u++)
                wmma::load_matrix_sync(af[u],
                    As + (wr * 32 + u * 16) * ALDH + kk, ALDH);
#pragma unroll
            for (int v = 0; v < 4; v++)
                wmma::load_matrix_sync(bf[v],
                    Bs + kk * BLDH + wc * 64 + v * 16, BLDH);
#pragma unroll
            for (int u = 0; u < 2; u++)
#pragma unroll
                for (int v = 0; v < 4; v++)
                    wmma::mma_sync(acc[u][v], af[u], bf[v], acc[u][v]);
        }
        __syncthreads();
    }

    if (!EPI) {
#pragma unroll
        for (int u = 0; u < 2; u++)
#pragma unroll
            for (int v = 0; v < 4; v++)
                wmma::store_matrix_sync(
                    Cout + (size_t)(row0 + wr * 32 + u * 16) * NOUT
                         + n0 + wc * 64 + v * 16,
                    acc[u][v], NOUT, wmma::mem_row_major);
    } else {
        // stage C (128 x 132 fp32) in smem, then bias + gelu . W2 row reduce
        float* Cs = (float*)smraw;
#pragma unroll
        for (int u = 0; u < 2; u++)
#pragma unroll
            for (int v = 0; v < 4; v++)
                wmma::store_matrix_sync(
                    Cs + (wr * 32 + u * 16) * 132 + wc * 64 + v * 16,
                    acc[u][v], 132, wmma::mem_row_major);
        __syncthreads();

        float b1f[4], w2f[4];
#pragma unroll
        for (int q = 0; q < 4; q++) {
            int gcol = n0 + lane + q * 32;
            b1f[q] = b1v[gcol];
            w2f[q] = W2v[gcol];
        }
#pragma unroll
        for (int rr = 0; rr < 16; rr++) {
            int r = warp * 16 + rr;
            float p = 0.f;
#pragma unroll
            for (int q = 0; q < 4; q++) {
                float x = Cs[r * 132 + lane + q * 32] + b1f[q];
                float h = 0.5f * x * (1.f + erff(x * 0.7071067811865476f));
                p = fmaf(h, w2f[q], p);
            }
#pragma unroll
            for (int off = 16; off > 0; off >>= 1)
                p += __shfl_xor_sync(0xffffffffu, p, off);
            if (lane == 0)
                g_plog[(size_t)(row0 + r) * NBLK_ + blockIdx.y] = p;
        }
    }
}

// ---------------------------------------------------------------------------
// LN pass: adds bias, LayerNorms in place. y=0 -> g_v (+g_rv), y=1 -> g_a.
// ---------------------------------------------------------------------------
__global__ __launch_bounds__(256) void ln_kernel(
    const float* __restrict__ bv, const float* __restrict__ ba)
{
    __shared__ float redS[8], redQ[8], bc2[2];
    const int row = blockIdx.x;
    const int d   = threadIdx.x;
    float* buf = blockIdx.y ? g_a : g_v;
    const float* bias = blockIdx.y ? ba : bv;

    float x = buf[(size_t)row * DM_ + d] + bias[d];
    float s = x, q = x * x;
#pragma unroll
    for (int off = 16; off > 0; off >>= 1) {
        s += __shfl_xor_sync(0xffffffffu, s, off);
        q += __shfl_xor_sync(0xffffffffu, q, off);
    }
    int lane = d & 31, warp = d >> 5;
    if (lane == 0) { redS[warp] = s; redQ[warp] = q; }
    __syncthreads();
    if (d == 0) {
        float ts = 0.f, tq = 0.f;
#pragma unroll
        for (int k = 0; k < 8; k++) { ts += redS[k]; tq += redQ[k]; }
        float mu  = ts * (1.f / 256.f);
        float var = fmaxf(tq * (1.f / 256.f) - mu * mu, 0.f);
        bc2[0] = mu;
        bc2[1] = rsqrtf(var + 1e-5f);
        if (blockIdx.y == 0) {
            float l2 = sqrtf(256.f * var) * bc2[1];
            g_rv[row] = 1.f / fmaxf(l2, 1e-8f);
        }
    }
    __syncthreads();
    buf[(size_t)row * DM_ + d] = (x - bc2[0]) * bc2[1];
}

// ---------------------------------------------------------------------------
// ctx: temporal shift + causal 6-tap window avg + l2 norms + build X (fp16).
// 4 rows/block, 64 threads/row, float4 per thread. center==t (delta in (2,6)).
// ---------------------------------------------------------------------------
__global__ __launch_bounds__(256) void ctx_kernel(const float* __restrict__ theta)
{
    __shared__ float red2[4][2];
    const int tid = threadIdx.x;
    const int rl  = tid >> 6;
    const int q   = tid & 63;
    const int row = blockIdx.x * 4 + rl;
    const int b   = row >> 11;
    const int t   = row & 2047;

    float th    = fminf(fmaxf(theta[0], -12.f), 12.f);
    float delta = 2.f + 4.f / (1.f + expf(-th));
    float nf    = floorf(delta);
    float alpha = delta - nf;
    int   ni    = (int)nf;

    const int lo = max(0, t - 5);
    const float inv_cnt = 1.f / (float)(t - lo + 1);

    const float* ab = g_a + (size_t)b * T_ * DM_;
    float4 acc = {0.f, 0.f, 0.f, 0.f};
    for (int tau = lo; tau <= t; tau++) {
        int i0 = min(max(tau - ni, 0), T_ - 1);
        int i1 = min(i0 + 1, T_ - 1);
        float4 x0 = *(const float4*)(ab + (size_t)i0 * DM_ + q * 4);
        float4 x1 = *(const float4*)(ab + (size_t)i1 * DM_ + q * 4);
        acc.x += (1.f - alpha) * x0.x + alpha * x1.x;
        acc.y += (1.f - alpha) * x0.y + alpha * x1.y;
        acc.z += (1.f - alpha) * x0.z + alpha * x1.z;
        acc.w += (1.f - alpha) * x0.w + alpha * x1.w;
    }
    float4 ac = {acc.x * inv_cnt, acc.y * inv_cnt, acc.z * inv_cnt, acc.w * inv_cnt};

    float ss = ac.x * ac.x + ac.y * ac.y + ac.z * ac.z + ac.w * ac.w;
#pragma unroll
    for (int off = 16; off > 0; off >>= 1)
        ss += __shfl_xor_sync(0xffffffffu, ss, off);
    const int wp = tid >> 5;
    if ((tid & 31) == 0) red2[wp >> 1][wp & 1] = ss;
    __syncthreads();
    float tot = red2[rl][0] + red2[rl][1];
    float ra  = 1.f / fmaxf(sqrtf(tot), 1e-8f);

    float4 vv = *(const float4*)(g_v + (size_t)row * DM_ + q * 4);
    float rv  = g_rv[row];

    *(float4*)(g_actx + (size_t)row * DM_ + q * 4) = ac;

    float vnx = vv.x * rv, vny = vv.y * rv, vnz = vv.z * rv, vnw = vv.w * rv;
    float anx = ac.x * ra, any_ = ac.y * ra, anz = ac.z * ra, anw = ac.w * ra;

    __half* xr = g_Xh + (size_t)row * XDIM_;
    *(uint2*)(xr + q * 4) =
        make_uint2(pkh2(anx, any_), pkh2(anz, anw));
    *(uint2*)(xr + DM_ + q * 4) =
        make_uint2(pkh2(vnx, vny), pkh2(vnz, vnw));
    *(uint2*)(xr + 2 * DM_ + q * 4) =
        make_uint2(pkh2(anx * vnx, any_ * vny), pkh2(anz * vnz, anw * vnw));
}

// ---------------------------------------------------------------------------
// out: finish logit, gate, mix. float4 per thread.
// ---------------------------------------------------------------------------
__global__ __launch_bounds__(256) void out_kernel(
    const float* __restrict__ b2, float* __restrict__ out)
{
    const int idx = blockIdx.x * 256 + threadIdx.x;   // over R_*64 float4s
    const int row = idx >> 6;
    const int c4  = (idx & 63) << 2;
    float s = b2[0];
#pragma unroll
    for (int k = 0; k < NBLK_; k++) s += g_plog[(size_t)row * NBLK_ + k];
    s = fminf(fmaxf(s, -12.f), 12.f);
    float g = 1.f / (1.f + expf(-s));
    g = fminf(fmaxf(g, 0.05f), 0.95f);
    float4 ac = *(const float4*)(g_actx + (size_t)row * DM_ + c4);
    float4 vv = *(const float4*)(g_v + (size_t)row * DM_ + c4);
    float4 o  = {g * ac.x + (1.f - g) * vv.x, g * ac.y + (1.f - g) * vv.y,
                 g * ac.z + (1.f - g) * vv.z, g * ac.w + (1.f - g) * vv.w};
    *(float4*)(out + (size_t)row * DM_ + c4) = o;
}

// ---------------------------------------------------------------------------
extern "C" void kernel_launch(void* const* d_in, const int* in_sizes, int n_in,
                              void* d_out, int out_size)
{
    const float* video = (const float*)d_in[0];
    const float* audio = (const float*)d_in[1];
    const float* Wv    = (const float*)d_in[2];
    const float* bv    = (const float*)d_in[3];
    const float* Wa    = (const float*)d_in[4];
    const float* ba    = (const float*)d_in[5];
    const float* theta = (const float*)d_in[6];
    const float* W1    = (const float*)d_in[7];
    const float* b1    = (const float*)d_in[8];
    const float* W2    = (const float*)d_in[9];
    const float* b2    = (const float*)d_in[10];
    float* out = (float*)d_out;

    float *gv, *ga;
    __half *gxh, *wv, *wa, *w1;
    cudaGetSymbolAddress((void**)&gv,  g_v);
    cudaGetSymbolAddress((void**)&ga,  g_a);
    cudaGetSymbolAddress((void**)&gxh, g_Xh);
    cudaGetSymbolAddress((void**)&wv,  g_wv);
    cudaGetSymbolAddress((void**)&wa,  g_wa);
    cudaGetSymbolAddress((void**)&w1,  g_w1);

    const int gsm = 2 * STGH * sizeof(__half);        // 37888 B
    const int msm = 128 * 132 * sizeof(float);        // 67584 B (epilogue C)
    cudaFuncSetAttribute(gemm_h<VDIM_/32, DM_, false, false>,
        cudaFuncAttributeMaxDynamicSharedMemorySize, gsm);
    cudaFuncSetAttribute(gemm_h<ADIM_/32, DM_, false, false>,
        cudaFuncAttributeMaxDynamicSharedMemorySize, gsm);
    cudaFuncSetAttribute(gemm_h<XDIM_/32, HID_, true, true>,
        cudaFuncAttributeMaxDynamicSharedMemorySize, msm);

    // weight prep (fp32 -> fp16)
    prep_wh<<<(VDIM_*DM_/4 + 255)/256, 256>>>(Wv, wv, VDIM_*DM_/4);
    prep_wh<<<(ADIM_*DM_/4 + 255)/256, 256>>>(Wa, wa, ADIM_*DM_/4);
    prep_wh<<<(XDIM_*HID_/4 + 255)/256, 256>>>(W1, w1, XDIM_*HID_/4);

    gemm_h<VDIM_/32, DM_, false, false><<<dim3(R_/128, 2), 256, gsm>>>(
        video, wv, nullptr, nullptr, gv);
    gemm_h<ADIM_/32, DM_, false, false><<<dim3(R_/128, 2), 256, gsm>>>(
        audio, wa, nullptr, nullptr, ga);
    ln_kernel<<<dim3(R_, 2), 256>>>(bv, ba);
    ctx_kernel<<<R_/4, 256>>>(theta);
    gemm_h<XDIM_/32, HID_, true, true><<<dim3(R_/128, NBLK_), 256, msm>>>(
        gxh, w1, b1, W2, nullptr);
    out_kernel<<<(R_*64)/256, 256>>>(b2, out);
}